// round 1
// baseline (speedup 1.0000x reference)
#include <cuda_runtime.h>
#include <math.h>

// ---------------- problem constants ----------------
#define NB   64      // batch
#define C0   64      // input channels
#define H0   56      // input H=W
#define FS   512     // filterset size (both layers)
#define HO   28      // output H=W (28x28)
#define CO   128     // proj output channels
#define KTOP 16      // sparsity
#define PIX  (NB*HO*HO)          // 50176 pixels
#define OUT_ELEMS (NB*CO*HO*HO)  // 6422528
#define X_ELEMS   (NB*C0*H0*H0)  // 12845056

#define NEG_BIG (-3.402823466e38f)

// ---------------- device scratch (static, no allocs) ----------------
__device__ float  g_act[PIX*FS];          // shared by layer0/layer1 activations
__device__ float  g_y0[OUT_ELEMS];        // raw proj0 conv output
__device__ float  g_y1[OUT_ELEMS];        // raw proj1 conv output
__device__ float  g_ysc[OUT_ELEMS];       // raw shortcut conv output
__device__ float  g_spv[2][PIX*KTOP];     // sparse values
__device__ int    g_spi[2][PIX*KTOP];     // sparse filter indices
__device__ float  g_wp_t[2][FS*CO];       // proj weights transposed [f][o]
__device__ float  g_wsc_t[C0*CO];         // shortcut weights transposed [c][o]
__device__ float  g_we0_t[C0*9*FS];       // enc0 weights transposed [(c,kh,kw)][f]
__device__ float  g_we1_t[CO*9*FS];       // enc1 weights transposed [(c,kh,kw)][f]
__device__ double g_sum[3][CO];
__device__ double g_sumsq[3][CO];
__device__ float  g_scale[3][CO];
__device__ float  g_shift[3][CO];
__device__ double g_aux_part[2][256];

// ---------------- init / transpose ----------------
__global__ void k_zero() {
    int t = threadIdx.x;
    if (t < CO) {
        for (int s = 0; s < 3; s++) { g_sum[s][t] = 0.0; g_sumsq[s][t] = 0.0; }
    }
    if (t < 256) { g_aux_part[0][t] = 0.0; g_aux_part[1][t] = 0.0; }
}

__global__ void k_tr_proj(const float* __restrict__ w, int which) {
    int i = blockIdx.x * 256 + threadIdx.x;
    if (i < FS * CO) {
        int o = i / FS, f = i % FS;
        g_wp_t[which][f * CO + o] = w[i];
    }
}

__global__ void k_tr_sc(const float* __restrict__ w) {
    int i = blockIdx.x * 256 + threadIdx.x;
    if (i < CO * C0) {
        int o = i / C0, c = i % C0;
        g_wsc_t[c * CO + o] = w[i];
    }
}

__global__ void k_tr_enc(const float* __restrict__ w, int which, int K) {
    int i = blockIdx.x * 256 + threadIdx.x;
    if (i < FS * K) {
        int f = i / K, k = i % K;
        float* dst = which ? g_we1_t : g_we0_t;
        dst[k * FS + f] = w[i];
    }
}

// ---------------- encoder conv 0: 3x3 stride 2, C0=64 -> FS=512 ----------------
// block = 512 threads (one filter each) x 7 pixels along w. grid = 64*28*4
__global__ __launch_bounds__(512) void k_conv_enc0(const float* __restrict__ x,
                                                   const float* __restrict__ w) {
    int b  = blockIdx.x;
    int wg = b & 3;
    int h  = (b >> 2) % 28;
    int n  = b / 112;
    int w0 = wg * 7;
    int f  = threadIdx.x;

    __shared__ float xs[3 * 64 * 15];   // [kh][c][col], col = 2p+kw
    int base_iw = 2 * w0 - 1;
    for (int i = f; i < 3 * 64 * 15; i += 512) {
        int l  = i % 15;
        int c  = (i / 15) % 64;
        int kh = i / (15 * 64);
        int ih = 2 * h + kh - 1;
        int iw = base_iw + l;
        float v = 0.f;
        if (ih >= 0 && ih < H0 && iw >= 0 && iw < H0)
            v = x[((n * C0 + c) * H0 + ih) * H0 + iw];
        xs[(kh * 64 + c) * 15 + l] = v;
    }
    __syncthreads();

    float acc[7];
    #pragma unroll
    for (int p = 0; p < 7; p++) acc[p] = 0.f;

    const float* wf = w + f * (C0 * 9);
    for (int c = 0; c < C0; c++) {
        float w9[9];
        #pragma unroll
        for (int q = 0; q < 9; q++) w9[q] = wf[c * 9 + q];
        #pragma unroll
        for (int kh = 0; kh < 3; kh++) {
            const float* xr = &xs[(kh * 64 + c) * 15];
            #pragma unroll
            for (int p = 0; p < 7; p++) {
                float s = acc[p];
                s += w9[kh * 3 + 0] * xr[2 * p + 0];
                s += w9[kh * 3 + 1] * xr[2 * p + 1];
                s += w9[kh * 3 + 2] * xr[2 * p + 2];
                acc[p] = s;
            }
        }
    }
    int p0 = (n * 28 + h) * 28 + w0;
    #pragma unroll
    for (int p = 0; p < 7; p++) g_act[(p0 + p) * FS + f] = acc[p];
}

// ---------------- encoder conv 1: 3x3 stride 1, CO=128 -> FS=512, input = BN0(y0)
__global__ __launch_bounds__(512) void k_conv_enc1(const float* __restrict__ w) {
    int b  = blockIdx.x;
    int wg = b & 3;
    int h  = (b >> 2) % 28;
    int n  = b / 112;
    int w0 = wg * 7;
    int f  = threadIdx.x;

    __shared__ float xs[3 * 128 * 9];  // [kh][c][col], col = p+kw
    for (int i = f; i < 3 * 128 * 9; i += 512) {
        int l  = i % 9;
        int c  = (i / 9) % 128;
        int kh = i / (9 * 128);
        int ih = h + kh - 1;
        int iw = w0 - 1 + l;
        float v = 0.f;
        if (ih >= 0 && ih < 28 && iw >= 0 && iw < 28)
            v = g_y0[((n * CO + c) * 28 + ih) * 28 + iw] * g_scale[0][c] + g_shift[0][c];
        xs[(kh * 128 + c) * 9 + l] = v;
    }
    __syncthreads();

    float acc[7];
    #pragma unroll
    for (int p = 0; p < 7; p++) acc[p] = 0.f;

    const float* wf = w + f * (CO * 9);
    for (int c = 0; c < CO; c++) {
        float w9[9];
        #pragma unroll
        for (int q = 0; q < 9; q++) w9[q] = wf[c * 9 + q];
        #pragma unroll
        for (int kh = 0; kh < 3; kh++) {
            const float* xr = &xs[(kh * 128 + c) * 9];
            #pragma unroll
            for (int p = 0; p < 7; p++) {
                float s = acc[p];
                s += w9[kh * 3 + 0] * xr[p + 0];
                s += w9[kh * 3 + 1] * xr[p + 1];
                s += w9[kh * 3 + 2] * xr[p + 2];
                acc[p] = s;
            }
        }
    }
    int p0 = (n * 28 + h) * 28 + w0;
    #pragma unroll
    for (int p = 0; p < 7; p++) g_act[(p0 + p) * FS + f] = acc[p];
}

// ---------------- per-pixel top-16 of 512 (one warp per pixel) ----------------
__global__ void k_topk(int layer) {
    int warp = (blockIdx.x * blockDim.x + threadIdx.x) >> 5;
    int lane = threadIdx.x & 31;
    if (warp >= PIX) return;
    const float* row = g_act + (size_t)warp * FS;
    float v[16];
    #pragma unroll
    for (int j = 0; j < 16; j++) v[j] = row[lane * 16 + j];

    float* ov = &g_spv[layer][warp * KTOP];
    int*   oi = &g_spi[layer][warp * KTOP];

    for (int it = 0; it < KTOP; it++) {
        float m = v[0]; int jm = 0;
        #pragma unroll
        for (int j = 1; j < 16; j++) if (v[j] > m) { m = v[j]; jm = j; }
        float bm = m; int bl = lane;
        #pragma unroll
        for (int off = 16; off; off >>= 1) {
            float om = __shfl_xor_sync(0xffffffffu, bm, off);
            int   ol = __shfl_xor_sync(0xffffffffu, bl, off);
            if (om > bm || (om == bm && ol < bl)) { bm = om; bl = ol; }
        }
        if (bl == lane) {
            ov[it] = m;
            oi[it] = lane * 16 + jm;
            v[jm] = NEG_BIG;
        }
    }
}

// ---------------- sparse 1x1 projection: y[n][o][h][w] = sum_j spv*wp_t[spi][o]
__global__ void k_proj(int layer) {
    int p0 = blockIdx.x * 8;
    __shared__ float sv[8][16];
    __shared__ int   si[8][16];
    int t = threadIdx.x;
    if (t < 128) {
        int pp = t / 16, j = t % 16;
        sv[pp][j] = g_spv[layer][(p0 + pp) * KTOP + j];
        si[pp][j] = g_spi[layer][(p0 + pp) * KTOP + j] * CO;
    }
    __syncthreads();
    const float* wp = g_wp_t[layer];
    float* y = layer ? g_y1 : g_y0;
    int o = t % 128, half = t / 128;
    for (int q = 0; q < 4; q++) {
        int pp = half * 4 + q;
        float acc = 0.f;
        #pragma unroll
        for (int j = 0; j < 16; j++) acc += sv[pp][j] * wp[si[pp][j] + o];
        int p = p0 + pp;
        int n = p / 784, hw = p % 784;
        y[(n * CO + o) * 784 + hw] = acc;
    }
}

// ---------------- shortcut 1x1 stride-2 conv ----------------
__global__ void k_shortcut(const float* __restrict__ x) {
    int pb = blockIdx.x;             // 2 pixels per block
    __shared__ float xsh[2][64];
    int t = threadIdx.x;
    if (t < 128) {
        int pp = t / 64, c = t % 64;
        int p = pb * 2 + pp;
        int n = p / 784, hw = p % 784;
        int h = hw / 28, w = hw % 28;
        xsh[pp][c] = x[((n * C0 + c) * H0 + 2 * h) * H0 + 2 * w];
    }
    __syncthreads();
    int o = t % 128, pp = t / 128;
    float acc = 0.f;
    #pragma unroll
    for (int c = 0; c < 64; c++) acc += xsh[pp][c] * g_wsc_t[c * CO + o];
    int p = pb * 2 + pp;
    int n = p / 784, hw = p % 784;
    g_ysc[(n * CO + o) * 784 + hw] = acc;
}

// ---------------- per-channel batch stats ----------------
__global__ void k_stats(int set) {
    const float* y = (set == 0) ? g_y0 : (set == 1) ? g_y1 : g_ysc;
    int o = blockIdx.x;
    int n0 = blockIdx.y * 8;
    float s = 0.f, s2 = 0.f;
    for (int n = n0; n < n0 + 8; n++) {
        const float* row = y + (size_t)(n * CO + o) * 784;
        for (int i = threadIdx.x; i < 784; i += 256) {
            float v = row[i]; s += v; s2 += v * v;
        }
    }
    __shared__ float sh[16];
    int lane = threadIdx.x & 31, wid = threadIdx.x >> 5;
    #pragma unroll
    for (int off = 16; off; off >>= 1) {
        s  += __shfl_down_sync(0xffffffffu, s, off);
        s2 += __shfl_down_sync(0xffffffffu, s2, off);
    }
    if (lane == 0) { sh[wid] = s; sh[wid + 8] = s2; }
    __syncthreads();
    if (threadIdx.x == 0) {
        float ts = 0.f, ts2 = 0.f;
        for (int w = 0; w < 8; w++) { ts += sh[w]; ts2 += sh[w + 8]; }
        atomicAdd(&g_sum[set][o], (double)ts);
        atomicAdd(&g_sumsq[set][o], (double)ts2);
    }
}

__global__ void k_finalize(int set, const float* __restrict__ g, const float* __restrict__ b) {
    int o = threadIdx.x;
    if (o < CO) {
        double M = (double)PIX;
        double mean = g_sum[set][o] / M;
        double var  = g_sumsq[set][o] / M - mean * mean;
        double sc = (double)g[o] / sqrt(var + 1e-5);
        g_scale[set][o] = (float)sc;
        g_shift[set][o] = (float)((double)b[o] - mean * sc);
    }
}

// ---------------- aux losses (exact conv adjoints, sparse gather) ----------------
__device__ __forceinline__ void block_acc_aux(float d, int which) {
    #pragma unroll
    for (int off = 16; off; off >>= 1) d += __shfl_down_sync(0xffffffffu, d, off);
    __shared__ float sh[8];
    int lane = threadIdx.x & 31, wid = threadIdx.x >> 5;
    if (lane == 0) sh[wid] = d;
    __syncthreads();
    if (threadIdx.x == 0) {
        float tot = 0.f;
        for (int w = 0; w < 8; w++) tot += sh[w];
        atomicAdd(&g_aux_part[which][blockIdx.x & 255], (double)tot);
    }
}

__global__ void k_aux0(const float* __restrict__ x) {
    int i = blockIdx.x * 256 + threadIdx.x;
    float d = 0.f;
    if (i < X_ELEMS) {
        int iw = i % 56;
        int t1 = i / 56;
        int ih = t1 % 56;
        int t2 = t1 / 56;
        int c  = t2 % 64;
        int n  = t2 / 64;
        float r = 0.f;
        #pragma unroll
        for (int kh = 0; kh < 3; kh++) {
            int th = ih + 1 - kh;
            if ((th & 1) || th < 0) continue;
            int oh = th >> 1;
            if (oh >= 28) continue;
            #pragma unroll
            for (int kw = 0; kw < 3; kw++) {
                int tw = iw + 1 - kw;
                if ((tw & 1) || tw < 0) continue;
                int ow = tw >> 1;
                if (ow >= 28) continue;
                int p = (n * 28 + oh) * 28 + ow;
                const float* vv = &g_spv[0][p * KTOP];
                const int*   ii = &g_spi[0][p * KTOP];
                const float* wt = &g_we0_t[(c * 9 + kh * 3 + kw) * FS];
                #pragma unroll
                for (int j = 0; j < 16; j++) r += vv[j] * wt[ii[j]];
            }
        }
        float df = r - x[i];
        d = df * df;
    }
    block_acc_aux(d, 0);
}

__global__ void k_aux1() {
    int i = blockIdx.x * 256 + threadIdx.x;   // over OUT_ELEMS exactly
    int iw = i % 28;
    int ih = (i / 28) % 28;
    int c  = (i / 784) % 128;
    int n  = i / (784 * 128);
    float r = 0.f;
    #pragma unroll
    for (int kh = 0; kh < 3; kh++) {
        int oh = ih + 1 - kh;
        if (oh < 0 || oh >= 28) continue;
        #pragma unroll
        for (int kw = 0; kw < 3; kw++) {
            int ow = iw + 1 - kw;
            if (ow < 0 || ow >= 28) continue;
            int p = (n * 28 + oh) * 28 + ow;
            const float* vv = &g_spv[1][p * KTOP];
            const int*   ii = &g_spi[1][p * KTOP];
            const float* wt = &g_we1_t[(c * 9 + kh * 3 + kw) * FS];
            #pragma unroll
            for (int j = 0; j < 16; j++) r += vv[j] * wt[ii[j]];
        }
    }
    float out0 = g_y0[i] * g_scale[0][c] + g_shift[0][c];
    float df = r - out0;
    block_acc_aux(df * df, 1);
}

// ---------------- final fuse: relu(BN1(y1) + BNsc(ysc)) ----------------
__global__ void k_final(float* __restrict__ out) {
    int i = blockIdx.x * 256 + threadIdx.x;   // OUT_ELEMS exactly
    int o = (i / 784) % 128;
    float a = g_y1[i]  * g_scale[1][o] + g_shift[1][o];
    float s = g_ysc[i] * g_scale[2][o] + g_shift[2][o];
    float v = a + s;
    out[i] = v > 0.f ? v : 0.f;
}

__global__ void k_auxwrite(float* __restrict__ out) {
    if (threadIdx.x == 0 && blockIdx.x == 0) {
        double s0 = 0.0, s1 = 0.0;
        for (int i = 0; i < 256; i++) { s0 += g_aux_part[0][i]; s1 += g_aux_part[1][i]; }
        out[OUT_ELEMS]     = (float)(s0 / (double)X_ELEMS);
        out[OUT_ELEMS + 1] = (float)(s1 / (double)OUT_ELEMS);
    }
}

// ---------------- launch ----------------
extern "C" void kernel_launch(void* const* d_in, const int* in_sizes, int n_in,
                              void* d_out, int out_size) {
    const float* x   = (const float*)d_in[0];
    const float* we0 = (const float*)d_in[1];
    const float* wp0 = (const float*)d_in[2];
    const float* g0  = (const float*)d_in[3];
    const float* b0  = (const float*)d_in[4];
    const float* we1 = (const float*)d_in[5];
    const float* wp1 = (const float*)d_in[6];
    const float* g1  = (const float*)d_in[7];
    const float* b1  = (const float*)d_in[8];
    const float* wsc = (const float*)d_in[9];
    const float* gsc = (const float*)d_in[10];
    const float* bsc = (const float*)d_in[11];
    float* out = (float*)d_out;

    (void)in_sizes; (void)n_in; (void)out_size;

    k_zero<<<1, 512>>>();
    k_tr_proj<<<(FS * CO + 255) / 256, 256>>>(wp0, 0);
    k_tr_proj<<<(FS * CO + 255) / 256, 256>>>(wp1, 1);
    k_tr_sc<<<(CO * C0 + 255) / 256, 256>>>(wsc);
    k_tr_enc<<<(FS * C0 * 9 + 255) / 256, 256>>>(we0, 0, C0 * 9);
    k_tr_enc<<<(FS * CO * 9 + 255) / 256, 256>>>(we1, 1, CO * 9);

    // layer 0
    k_conv_enc0<<<NB * 28 * 4, 512>>>(x, we0);
    k_topk<<<(PIX * 32 + 255) / 256, 256>>>(0);
    k_proj<<<PIX / 8, 256>>>(0);
    {
        dim3 g(CO, 8);
        k_stats<<<g, 256>>>(0);
    }
    k_finalize<<<1, 128>>>(0, g0, b0);

    // layer 1 (reads BN0(y0) on the fly)
    k_conv_enc1<<<NB * 28 * 4, 512>>>(we1);
    k_topk<<<(PIX * 32 + 255) / 256, 256>>>(1);
    k_proj<<<PIX / 8, 256>>>(1);
    {
        dim3 g(CO, 8);
        k_stats<<<g, 256>>>(1);
    }
    k_finalize<<<1, 128>>>(1, g1, b1);

    // shortcut
    k_shortcut<<<PIX / 2, 256>>>(x);
    {
        dim3 g(CO, 8);
        k_stats<<<g, 256>>>(2);
    }
    k_finalize<<<1, 128>>>(2, gsc, bsc);

    // aux losses
    k_aux0<<<(X_ELEMS + 255) / 256, 256>>>(x);
    k_aux1<<<OUT_ELEMS / 256, 256>>>();

    // output
    k_final<<<OUT_ELEMS / 256, 256>>>(out);
    k_auxwrite<<<1, 32>>>(out);
}

// round 2
// speedup vs baseline: 7.5812x; 7.5812x over previous
#include <cuda_runtime.h>
#include <math.h>

// ---------------- problem constants ----------------
#define NB   64      // batch
#define C0   64      // input channels
#define H0   56      // input H=W
#define FS   512     // filterset size (both layers)
#define HO   28      // output H=W (28x28)
#define CO   128     // proj output channels
#define KTOP 16      // sparsity
#define PIX  (NB*HO*HO)          // 50176 pixels
#define OUT_ELEMS (NB*CO*HO*HO)  // 6422528
#define X_ELEMS   (NB*C0*H0*H0)  // 12845056

#define NEG_BIG (-3.402823466e38f)

// ---------------- device scratch (static, no allocs) ----------------
__device__ float  g_act[PIX*FS];          // shared by layer0/layer1 activations
__device__ float  g_y0[OUT_ELEMS];        // raw proj0 conv output
__device__ float  g_y1[OUT_ELEMS];        // raw proj1 conv output
__device__ float  g_ysc[OUT_ELEMS];       // raw shortcut conv output
__device__ float  g_spv[2][PIX*KTOP];     // sparse values
__device__ int    g_spi[2][PIX*KTOP];     // sparse filter indices
__device__ float  g_wp_t[2][FS*CO];       // proj weights transposed [f][o]
__device__ float  g_wsc_t[C0*CO];         // shortcut weights transposed [c][o]
__device__ float  g_we0_t[C0*9*FS];       // enc0 weights transposed [(c,kh,kw)][f]
__device__ float  g_we1_t[CO*9*FS];       // enc1 weights transposed [(c,kh,kw)][f]
__device__ float  g_wr0[FS*9*C0];         // enc0 weights [f][k][c] (c contiguous)
__device__ float  g_wr1[FS*9*CO];         // enc1 weights [f][k][c] (c contiguous)
__device__ double g_sum[3][CO];
__device__ double g_sumsq[3][CO];
__device__ float  g_scale[3][CO];
__device__ float  g_shift[3][CO];
__device__ double g_aux_part[2][256];

// ---------------- init / transpose ----------------
__global__ void k_zero() {
    int t = threadIdx.x;
    if (t < CO) {
        for (int s = 0; s < 3; s++) { g_sum[s][t] = 0.0; g_sumsq[s][t] = 0.0; }
    }
    if (t < 256) { g_aux_part[0][t] = 0.0; g_aux_part[1][t] = 0.0; }
}

__global__ void k_tr_proj(const float* __restrict__ w, int which) {
    int i = blockIdx.x * 256 + threadIdx.x;
    if (i < FS * CO) {
        int o = i / FS, f = i % FS;
        g_wp_t[which][f * CO + o] = w[i];
    }
}

__global__ void k_tr_sc(const float* __restrict__ w) {
    int i = blockIdx.x * 256 + threadIdx.x;
    if (i < CO * C0) {
        int o = i / C0, c = i % C0;
        g_wsc_t[c * CO + o] = w[i];
    }
}

// produces both layouts used downstream:
//   g_we*_t[(c*9+k)*FS + f]  (conv kernels, f contiguous)
//   g_wr*  [(f*9+k)*C  + c]  (aux kernels,  c contiguous)
__global__ void k_tr_enc(const float* __restrict__ w, int which, int C) {
    int i = blockIdx.x * 256 + threadIdx.x;
    if (i < FS * C * 9) {
        int K = C * 9;
        int f = i / K;
        int rem = i % K;          // = c*9 + k
        int c = rem / 9, k = rem % 9;
        float v = w[i];
        if (which) {
            g_we1_t[(c * 9 + k) * FS + f] = v;
            g_wr1[(f * 9 + k) * CO + c] = v;
        } else {
            g_we0_t[(c * 9 + k) * FS + f] = v;
            g_wr0[(f * 9 + k) * C0 + c] = v;
        }
    }
}

// ---------------- encoder conv 0: 3x3 stride 2, C0=64 -> FS=512 ----------------
// block = 512 threads (one filter each) x 28 pixels (full output row). grid = 64*28
__global__ __launch_bounds__(512) void k_conv_enc0(const float* __restrict__ x) {
    int b = blockIdx.x;
    int h = b % 28;
    int n = b / 28;
    int f = threadIdx.x;

    __shared__ float xs[3 * 64 * 57];   // [kh][c][col], col = 2p+kw  (iw = col-1)
    for (int i = f; i < 3 * 64 * 57; i += 512) {
        int l  = i % 57;
        int c  = (i / 57) % 64;
        int kh = i / (57 * 64);
        int ih = 2 * h + kh - 1;
        int iw = l - 1;
        float v = 0.f;
        if (ih >= 0 && ih < H0 && iw >= 0 && iw < H0)
            v = x[((n * C0 + c) * H0 + ih) * H0 + iw];
        xs[(kh * 64 + c) * 57 + l] = v;
    }
    __syncthreads();

    float acc[28];
    #pragma unroll
    for (int p = 0; p < 28; p++) acc[p] = 0.f;

    for (int c = 0; c < C0; c++) {
        float w9[9];
        #pragma unroll
        for (int q = 0; q < 9; q++) w9[q] = g_we0_t[(c * 9 + q) * FS + f];
        #pragma unroll
        for (int kh = 0; kh < 3; kh++) {
            const float* xr = &xs[(kh * 64 + c) * 57];
            #pragma unroll
            for (int p = 0; p < 28; p++) {
                float s = acc[p];
                s += w9[kh * 3 + 0] * xr[2 * p + 0];
                s += w9[kh * 3 + 1] * xr[2 * p + 1];
                s += w9[kh * 3 + 2] * xr[2 * p + 2];
                acc[p] = s;
            }
        }
    }
    int p0 = (n * 28 + h) * 28;
    #pragma unroll
    for (int p = 0; p < 28; p++) g_act[(size_t)(p0 + p) * FS + f] = acc[p];
}

// ---------------- encoder conv 1: 3x3 stride 1, CO=128 -> FS=512, input = BN0(y0)
__global__ __launch_bounds__(512) void k_conv_enc1() {
    int b = blockIdx.x;
    int h = b % 28;
    int n = b / 28;
    int f = threadIdx.x;

    __shared__ float xs[3 * 128 * 30];  // [kh][c][col], col = p+kw  (iw = col-1)
    for (int i = f; i < 3 * 128 * 30; i += 512) {
        int l  = i % 30;
        int c  = (i / 30) % 128;
        int kh = i / (30 * 128);
        int ih = h + kh - 1;
        int iw = l - 1;
        float v = 0.f;
        if (ih >= 0 && ih < 28 && iw >= 0 && iw < 28)
            v = g_y0[((n * CO + c) * 28 + ih) * 28 + iw] * g_scale[0][c] + g_shift[0][c];
        xs[(kh * 128 + c) * 30 + l] = v;
    }
    __syncthreads();

    float acc[28];
    #pragma unroll
    for (int p = 0; p < 28; p++) acc[p] = 0.f;

    for (int c = 0; c < CO; c++) {
        float w9[9];
        #pragma unroll
        for (int q = 0; q < 9; q++) w9[q] = g_we1_t[(c * 9 + q) * FS + f];
        #pragma unroll
        for (int kh = 0; kh < 3; kh++) {
            const float* xr = &xs[(kh * 128 + c) * 30];
            #pragma unroll
            for (int p = 0; p < 28; p++) {
                float s = acc[p];
                s += w9[kh * 3 + 0] * xr[p + 0];
                s += w9[kh * 3 + 1] * xr[p + 1];
                s += w9[kh * 3 + 2] * xr[p + 2];
                acc[p] = s;
            }
        }
    }
    int p0 = (n * 28 + h) * 28;
    #pragma unroll
    for (int p = 0; p < 28; p++) g_act[(size_t)(p0 + p) * FS + f] = acc[p];
}

// ---------------- per-pixel top-16 of 512 (one warp per pixel) ----------------
__global__ void k_topk(int layer) {
    int warp = (blockIdx.x * blockDim.x + threadIdx.x) >> 5;
    int lane = threadIdx.x & 31;
    if (warp >= PIX) return;
    const float* row = g_act + (size_t)warp * FS;
    float v[16];
    #pragma unroll
    for (int j = 0; j < 16; j++) v[j] = row[lane * 16 + j];

    float* ov = &g_spv[layer][warp * KTOP];
    int*   oi = &g_spi[layer][warp * KTOP];

    for (int it = 0; it < KTOP; it++) {
        float m = v[0]; int jm = 0;
        #pragma unroll
        for (int j = 1; j < 16; j++) if (v[j] > m) { m = v[j]; jm = j; }
        float bm = m; int bl = lane;
        #pragma unroll
        for (int off = 16; off; off >>= 1) {
            float om = __shfl_xor_sync(0xffffffffu, bm, off);
            int   ol = __shfl_xor_sync(0xffffffffu, bl, off);
            if (om > bm || (om == bm && ol < bl)) { bm = om; bl = ol; }
        }
        if (bl == lane) {
            ov[it] = m;
            oi[it] = lane * 16 + jm;
            v[jm] = NEG_BIG;
        }
    }
}

// ---------------- sparse 1x1 projection: y[n][o][h][w] = sum_j spv*wp_t[spi][o]
__global__ void k_proj(int layer) {
    int p0 = blockIdx.x * 8;
    __shared__ float sv[8][16];
    __shared__ int   si[8][16];
    int t = threadIdx.x;
    if (t < 128) {
        int pp = t / 16, j = t % 16;
        sv[pp][j] = g_spv[layer][(p0 + pp) * KTOP + j];
        si[pp][j] = g_spi[layer][(p0 + pp) * KTOP + j] * CO;
    }
    __syncthreads();
    const float* wp = g_wp_t[layer];
    float* y = layer ? g_y1 : g_y0;
    int o = t % 128, half = t / 128;
    for (int q = 0; q < 4; q++) {
        int pp = half * 4 + q;
        float acc = 0.f;
        #pragma unroll
        for (int j = 0; j < 16; j++) acc += sv[pp][j] * wp[si[pp][j] + o];
        int p = p0 + pp;
        int n = p / 784, hw = p % 784;
        y[(n * CO + o) * 784 + hw] = acc;
    }
}

// ---------------- shortcut 1x1 stride-2 conv ----------------
__global__ void k_shortcut(const float* __restrict__ x) {
    int pb = blockIdx.x;             // 2 pixels per block
    __shared__ float xsh[2][64];
    int t = threadIdx.x;
    if (t < 128) {
        int pp = t / 64, c = t % 64;
        int p = pb * 2 + pp;
        int n = p / 784, hw = p % 784;
        int h = hw / 28, w = hw % 28;
        xsh[pp][c] = x[((n * C0 + c) * H0 + 2 * h) * H0 + 2 * w];
    }
    __syncthreads();
    int o = t % 128, pp = t / 128;
    float acc = 0.f;
    #pragma unroll
    for (int c = 0; c < 64; c++) acc += xsh[pp][c] * g_wsc_t[c * CO + o];
    int p = pb * 2 + pp;
    int n = p / 784, hw = p % 784;
    g_ysc[(n * CO + o) * 784 + hw] = acc;
}

// ---------------- per-channel batch stats ----------------
__global__ void k_stats(int set) {
    const float* y = (set == 0) ? g_y0 : (set == 1) ? g_y1 : g_ysc;
    int o = blockIdx.x;
    int n0 = blockIdx.y * 8;
    float s = 0.f, s2 = 0.f;
    for (int n = n0; n < n0 + 8; n++) {
        const float* row = y + (size_t)(n * CO + o) * 784;
        for (int i = threadIdx.x; i < 784; i += 256) {
            float v = row[i]; s += v; s2 += v * v;
        }
    }
    __shared__ float sh[16];
    int lane = threadIdx.x & 31, wid = threadIdx.x >> 5;
    #pragma unroll
    for (int off = 16; off; off >>= 1) {
        s  += __shfl_down_sync(0xffffffffu, s, off);
        s2 += __shfl_down_sync(0xffffffffu, s2, off);
    }
    if (lane == 0) { sh[wid] = s; sh[wid + 8] = s2; }
    __syncthreads();
    if (threadIdx.x == 0) {
        float ts = 0.f, ts2 = 0.f;
        for (int w = 0; w < 8; w++) { ts += sh[w]; ts2 += sh[w + 8]; }
        atomicAdd(&g_sum[set][o], (double)ts);
        atomicAdd(&g_sumsq[set][o], (double)ts2);
    }
}

__global__ void k_finalize(int set, const float* __restrict__ g, const float* __restrict__ b) {
    int o = threadIdx.x;
    if (o < CO) {
        double M = (double)PIX;
        double mean = g_sum[set][o] / M;
        double var  = g_sumsq[set][o] / M - mean * mean;
        double sc = (double)g[o] / sqrt(var + 1e-5);
        g_scale[set][o] = (float)sc;
        g_shift[set][o] = (float)((double)b[o] - mean * sc);
    }
}

// ---------------- aux losses (exact conv adjoints, coalesced c-parallel gather)
// aux0: block = 64 threads (one per input channel c), one input pixel per block.
__global__ __launch_bounds__(64) void k_aux0(const float* __restrict__ x) {
    int b  = blockIdx.x;                 // n*56*56 + ih*56 + iw
    int iw = b % 56;
    int ih = (b / 56) % 56;
    int n  = b / (56 * 56);
    int t  = threadIdx.x;                // c

    __shared__ float sv[9][16];
    __shared__ int   si[9][16];

    // cooperative load of sparse codes for valid taps
    for (int idx = t; idx < 144; idx += 64) {
        int kk = idx / 16, j = idx % 16;
        int kh = kk / 3, kw = kk % 3;
        int th = ih + 1 - kh, tw = iw + 1 - kw;
        if (!(th & 1) && !(tw & 1) && th >= 0 && tw >= 0) {
            int oh = th >> 1, ow = tw >> 1;
            if (oh < 28 && ow < 28) {
                int p = (n * 28 + oh) * 28 + ow;
                sv[kk][j] = g_spv[0][p * KTOP + j];
                si[kk][j] = g_spi[0][p * KTOP + j] * (9 * C0);
            }
        }
    }
    __syncthreads();

    float r = 0.f;
    #pragma unroll
    for (int kk = 0; kk < 9; kk++) {
        int kh = kk / 3, kw = kk % 3;
        int th = ih + 1 - kh, tw = iw + 1 - kw;
        if ((th & 1) || (tw & 1) || th < 0 || tw < 0) continue;
        if ((th >> 1) >= 28 || (tw >> 1) >= 28) continue;
        const float* wb = g_wr0 + kk * C0 + t;
        #pragma unroll
        for (int j = 0; j < 16; j++) r += sv[kk][j] * wb[si[kk][j]];
    }
    float df = r - x[((n * C0 + t) * H0 + ih) * H0 + iw];
    float d = df * df;

    // reduce over 64 threads (2 warps)
    #pragma unroll
    for (int off = 16; off; off >>= 1) d += __shfl_down_sync(0xffffffffu, d, off);
    __shared__ float sh[2];
    int lane = t & 31, wid = t >> 5;
    if (lane == 0) sh[wid] = d;
    __syncthreads();
    if (t == 0) atomicAdd(&g_aux_part[0][b & 255], (double)(sh[0] + sh[1]));
}

// aux1: block = 128 threads (one per channel c), one pixel per block.
__global__ __launch_bounds__(128) void k_aux1() {
    int p  = blockIdx.x;                 // 0..PIX-1
    int hw = p % 784;
    int n  = p / 784;
    int ih = hw / 28, iw = hw % 28;
    int t  = threadIdx.x;                // c

    __shared__ float sv[9][16];
    __shared__ int   si[9][16];

    for (int idx = t; idx < 144; idx += 128) {
        int kk = idx / 16, j = idx % 16;
        int kh = kk / 3, kw = kk % 3;
        int oh = ih + 1 - kh, ow = iw + 1 - kw;
        if (oh >= 0 && oh < 28 && ow >= 0 && ow < 28) {
            int pp = (n * 28 + oh) * 28 + ow;
            sv[kk][j] = g_spv[1][pp * KTOP + j];
            si[kk][j] = g_spi[1][pp * KTOP + j] * (9 * CO);
        }
    }
    __syncthreads();

    float r = 0.f;
    #pragma unroll
    for (int kk = 0; kk < 9; kk++) {
        int kh = kk / 3, kw = kk % 3;
        int oh = ih + 1 - kh, ow = iw + 1 - kw;
        if (oh < 0 || oh >= 28 || ow < 0 || ow >= 28) continue;
        const float* wb = g_wr1 + kk * CO + t;
        #pragma unroll
        for (int j = 0; j < 16; j++) r += sv[kk][j] * wb[si[kk][j]];
    }
    float out0 = g_y0[((n * CO + t) * 28 + ih) * 28 + iw] * g_scale[0][t] + g_shift[0][t];
    float df = r - out0;
    float d = df * df;

    #pragma unroll
    for (int off = 16; off; off >>= 1) d += __shfl_down_sync(0xffffffffu, d, off);
    __shared__ float sh[4];
    int lane = t & 31, wid = t >> 5;
    if (lane == 0) sh[wid] = d;
    __syncthreads();
    if (t == 0) atomicAdd(&g_aux_part[1][p & 255], (double)(sh[0] + sh[1] + sh[2] + sh[3]));
}

// ---------------- final fuse: relu(BN1(y1) + BNsc(ysc)) ----------------
__global__ void k_final(float* __restrict__ out) {
    int i = blockIdx.x * 256 + threadIdx.x;   // OUT_ELEMS exactly
    int o = (i / 784) % 128;
    float a = g_y1[i]  * g_scale[1][o] + g_shift[1][o];
    float s = g_ysc[i] * g_scale[2][o] + g_shift[2][o];
    float v = a + s;
    out[i] = v > 0.f ? v : 0.f;
}

__global__ void k_auxwrite(float* __restrict__ out) {
    if (threadIdx.x == 0 && blockIdx.x == 0) {
        double s0 = 0.0, s1 = 0.0;
        for (int i = 0; i < 256; i++) { s0 += g_aux_part[0][i]; s1 += g_aux_part[1][i]; }
        out[OUT_ELEMS]     = (float)(s0 / (double)X_ELEMS);
        out[OUT_ELEMS + 1] = (float)(s1 / (double)OUT_ELEMS);
    }
}

// ---------------- launch ----------------
extern "C" void kernel_launch(void* const* d_in, const int* in_sizes, int n_in,
                              void* d_out, int out_size) {
    const float* x   = (const float*)d_in[0];
    const float* we0 = (const float*)d_in[1];
    const float* wp0 = (const float*)d_in[2];
    const float* g0  = (const float*)d_in[3];
    const float* b0  = (const float*)d_in[4];
    const float* we1 = (const float*)d_in[5];
    const float* wp1 = (const float*)d_in[6];
    const float* g1  = (const float*)d_in[7];
    const float* b1  = (const float*)d_in[8];
    const float* wsc = (const float*)d_in[9];
    const float* gsc = (const float*)d_in[10];
    const float* bsc = (const float*)d_in[11];
    float* out = (float*)d_out;

    (void)in_sizes; (void)n_in; (void)out_size;

    k_zero<<<1, 512>>>();
    k_tr_proj<<<(FS * CO + 255) / 256, 256>>>(wp0, 0);
    k_tr_proj<<<(FS * CO + 255) / 256, 256>>>(wp1, 1);
    k_tr_sc<<<(CO * C0 + 255) / 256, 256>>>(wsc);
    k_tr_enc<<<(FS * C0 * 9 + 255) / 256, 256>>>(we0, 0, C0);
    k_tr_enc<<<(FS * CO * 9 + 255) / 256, 256>>>(we1, 1, CO);

    // layer 0
    k_conv_enc0<<<NB * 28, 512>>>(x);
    k_topk<<<(PIX * 32 + 255) / 256, 256>>>(0);
    k_proj<<<PIX / 8, 256>>>(0);
    {
        dim3 g(CO, 8);
        k_stats<<<g, 256>>>(0);
    }
    k_finalize<<<1, 128>>>(0, g0, b0);

    // layer 1 (reads BN0(y0) on the fly)
    k_conv_enc1<<<NB * 28, 512>>>();
    k_topk<<<(PIX * 32 + 255) / 256, 256>>>(1);
    k_proj<<<PIX / 8, 256>>>(1);
    {
        dim3 g(CO, 8);
        k_stats<<<g, 256>>>(1);
    }
    k_finalize<<<1, 128>>>(1, g1, b1);

    // shortcut
    k_shortcut<<<PIX / 2, 256>>>(x);
    {
        dim3 g(CO, 8);
        k_stats<<<g, 256>>>(2);
    }
    k_finalize<<<1, 128>>>(2, gsc, bsc);

    // aux losses
    k_aux0<<<NB * H0 * H0, 64>>>(x);
    k_aux1<<<PIX, 128>>>();

    // output
    k_final<<<OUT_ELEMS / 256, 256>>>(out);
    k_auxwrite<<<1, 32>>>(out);
}

// round 4
// speedup vs baseline: 9.3414x; 1.2322x over previous
#include <cuda_runtime.h>
#include <math.h>

// ---------------- problem constants ----------------
#define NB   64      // batch
#define C0   64      // input channels
#define H0   56      // input H=W
#define FS   512     // filterset size (both layers)
#define HO   28      // output H=W (28x28)
#define CO   128     // proj output channels
#define KTOP 16      // sparsity
#define PIX  (NB*HO*HO)          // 50176 pixels
#define OUT_ELEMS (NB*CO*HO*HO)  // 6422528
#define X_ELEMS   (NB*C0*H0*H0)  // 12845056

#define NEG_BIG (-3.402823466e38f)

typedef unsigned long long u64;

// packed f32x2 fused multiply-add (Blackwell packed-fp32 datapath)
static __device__ __forceinline__ u64 ffma2(u64 a, u64 b, u64 c) {
    u64 d;
    asm("fma.rn.f32x2 %0, %1, %2, %3;" : "=l"(d) : "l"(a), "l"(b), "l"(c));
    return d;
}

// ---------------- device scratch (static, no allocs) ----------------
__device__ float  g_act[PIX*FS];          // shared by layer0/layer1 activations
__device__ float  g_y0[OUT_ELEMS];        // raw proj0 conv output
__device__ float  g_y1[OUT_ELEMS];        // raw proj1 conv output
__device__ float  g_ysc[OUT_ELEMS];       // raw shortcut conv output
__device__ float  g_spv[2][PIX*KTOP];     // sparse values
__device__ int    g_spi[2][PIX*KTOP];     // sparse filter indices
__device__ float  g_wp_t[2][FS*CO];       // proj weights transposed [f][o]
__device__ float  g_wsc_t[C0*CO];         // shortcut weights transposed [c][o]
__device__ u64    g_we0_p[C0*9*FS];       // enc0 weights [(c,k)][f] packed (w,w)
__device__ u64    g_we1_p[CO*9*FS];       // enc1 weights [(c,k)][f] packed (w,w)
__device__ float  g_wr0[FS*9*C0];         // enc0 weights [f][k][c] (c contiguous)
__device__ float  g_wr1[FS*9*CO];         // enc1 weights [f][k][c] (c contiguous)
__device__ double g_sum[3][CO];
__device__ double g_sumsq[3][CO];
__device__ float  g_scale[3][CO];
__device__ float  g_shift[3][CO];
__device__ double g_aux_part[2][256];

// ---------------- init / transpose ----------------
__global__ void k_zero() {
    int t = threadIdx.x;
    if (t < CO) {
        for (int s = 0; s < 3; s++) { g_sum[s][t] = 0.0; g_sumsq[s][t] = 0.0; }
    }
    if (t < 256) { g_aux_part[0][t] = 0.0; g_aux_part[1][t] = 0.0; }
}

__global__ void k_tr_proj(const float* __restrict__ w, int which) {
    int i = blockIdx.x * 256 + threadIdx.x;
    if (i < FS * CO) {
        int o = i / FS, f = i % FS;
        g_wp_t[which][f * CO + o] = w[i];
    }
}

__global__ void k_tr_sc(const float* __restrict__ w) {
    int i = blockIdx.x * 256 + threadIdx.x;
    if (i < CO * C0) {
        int o = i / C0, c = i % C0;
        g_wsc_t[c * CO + o] = w[i];
    }
}

// produces both layouts used downstream:
//   g_we*_p[(c*9+k)*FS + f]  (conv kernels, f contiguous, packed (w,w))
//   g_wr*  [(f*9+k)*C  + c]  (aux kernels,  c contiguous)
__global__ void k_tr_enc(const float* __restrict__ w, int which, int C) {
    int i = blockIdx.x * 256 + threadIdx.x;
    if (i < FS * C * 9) {
        int K = C * 9;
        int f = i / K;
        int rem = i % K;          // = c*9 + k
        int c = rem / 9, k = rem % 9;
        float v = w[i];
        unsigned u = __float_as_uint(v);
        u64 pv = (((u64)u) << 32) | (u64)u;
        if (which) {
            g_we1_p[(c * 9 + k) * FS + f] = pv;
            g_wr1[(f * 9 + k) * CO + c] = v;
        } else {
            g_we0_p[(c * 9 + k) * FS + f] = pv;
            g_wr0[(f * 9 + k) * C0 + c] = v;
        }
    }
}

// ---------------- encoder conv 0: 3x3 stride 2, C0=64 -> FS=512 ----------------
// block = 512 threads (one filter each) x 2 output rows x 28 cols. grid = 64*14.
// smem holds packed pairs: ps[kh][cc][l].x = x row (2h0+kh-1), .y = x row (2h0+kh+1)
#define E0_CCH 32
__global__ __launch_bounds__(512) void k_conv_enc0(const float* __restrict__ x) {
    int b  = blockIdx.x;
    int h0 = (b % 14) * 2;
    int n  = b / 14;
    int f  = threadIdx.x;

    __shared__ u64 ps[3 * E0_CCH * 57];

    u64 acc[28];
    #pragma unroll
    for (int p = 0; p < 28; p++) acc[p] = 0ull;

    for (int ch0 = 0; ch0 < C0; ch0 += E0_CCH) {
        __syncthreads();
        for (int i = f; i < 3 * E0_CCH * 57 * 2; i += 512) {
            int half = i & 1;
            int j    = i >> 1;
            int l    = j % 57;
            int cc   = (j / 57) % E0_CCH;
            int kh   = j / (57 * E0_CCH);
            int c    = ch0 + cc;
            int row  = 2 * h0 + kh - 1 + 2 * half;
            int iw   = l - 1;
            float v = 0.f;
            if (row >= 0 && row < H0 && iw >= 0 && iw < H0)
                v = x[((n * C0 + c) * H0 + row) * H0 + iw];
            ((float*)ps)[i] = v;
        }
        __syncthreads();

        for (int cc = 0; cc < E0_CCH; cc++) {
            int c = ch0 + cc;
            u64 w2[9];
            #pragma unroll
            for (int q = 0; q < 9; q++) w2[q] = g_we0_p[(c * 9 + q) * FS + f];
            #pragma unroll
            for (int kh = 0; kh < 3; kh++) {
                const u64* xr = &ps[(kh * E0_CCH + cc) * 57];
                #pragma unroll
                for (int p = 0; p < 28; p++) {
                    acc[p] = ffma2(w2[kh * 3 + 0], xr[2 * p + 0], acc[p]);
                    acc[p] = ffma2(w2[kh * 3 + 1], xr[2 * p + 1], acc[p]);
                    acc[p] = ffma2(w2[kh * 3 + 2], xr[2 * p + 2], acc[p]);
                }
            }
        }
    }

    int p0 = (n * 28 + h0) * 28;
    int p1 = p0 + 28;
    #pragma unroll
    for (int p = 0; p < 28; p++) {
        g_act[(size_t)(p0 + p) * FS + f] = __uint_as_float((unsigned)acc[p]);
        g_act[(size_t)(p1 + p) * FS + f] = __uint_as_float((unsigned)(acc[p] >> 32));
    }
}

// ---------------- encoder conv 1: 3x3 stride 1, CO=128 -> FS=512, input = BN0(y0)
// smem packed pairs: ps[kh][cc][l].x = row (h0+kh-1), .y = row (h0+kh)
#define E1_CCH 32
__global__ __launch_bounds__(512) void k_conv_enc1() {
    int b  = blockIdx.x;
    int h0 = (b % 14) * 2;
    int n  = b / 14;
    int f  = threadIdx.x;

    __shared__ u64 ps[3 * E1_CCH * 30];

    u64 acc[28];
    #pragma unroll
    for (int p = 0; p < 28; p++) acc[p] = 0ull;

    for (int ch0 = 0; ch0 < CO; ch0 += E1_CCH) {
        __syncthreads();
        for (int i = f; i < 3 * E1_CCH * 30 * 2; i += 512) {
            int half = i & 1;
            int j    = i >> 1;
            int l    = j % 30;
            int cc   = (j / 30) % E1_CCH;
            int kh   = j / (30 * E1_CCH);
            int c    = ch0 + cc;
            int row  = h0 + kh - 1 + half;
            int iw   = l - 1;
            float v = 0.f;
            if (row >= 0 && row < 28 && iw >= 0 && iw < 28)
                v = g_y0[((n * CO + c) * 28 + row) * 28 + iw] * g_scale[0][c] + g_shift[0][c];
            ((float*)ps)[i] = v;
        }
        __syncthreads();

        for (int cc = 0; cc < E1_CCH; cc++) {
            int c = ch0 + cc;
            u64 w2[9];
            #pragma unroll
            for (int q = 0; q < 9; q++) w2[q] = g_we1_p[(c * 9 + q) * FS + f];
            #pragma unroll
            for (int kh = 0; kh < 3; kh++) {
                const u64* xr = &ps[(kh * E1_CCH + cc) * 30];
                #pragma unroll
                for (int p = 0; p < 28; p++) {
                    acc[p] = ffma2(w2[kh * 3 + 0], xr[p + 0], acc[p]);
                    acc[p] = ffma2(w2[kh * 3 + 1], xr[p + 1], acc[p]);
                    acc[p] = ffma2(w2[kh * 3 + 2], xr[p + 2], acc[p]);
                }
            }
        }
    }

    int p0 = (n * 28 + h0) * 28;
    int p1 = p0 + 28;
    #pragma unroll
    for (int p = 0; p < 28; p++) {
        g_act[(size_t)(p0 + p) * FS + f] = __uint_as_float((unsigned)acc[p]);
        g_act[(size_t)(p1 + p) * FS + f] = __uint_as_float((unsigned)(acc[p] >> 32));
    }
}

// ---------------- per-pixel top-16 of 512 (one warp per pixel) ----------------
__global__ void k_topk(int layer) {
    int warp = (blockIdx.x * blockDim.x + threadIdx.x) >> 5;
    int lane = threadIdx.x & 31;
    if (warp >= PIX) return;
    const float* row = g_act + (size_t)warp * FS;
    float v[16];
    #pragma unroll
    for (int j = 0; j < 16; j++) v[j] = row[lane * 16 + j];

    float* ov = &g_spv[layer][warp * KTOP];
    int*   oi = &g_spi[layer][warp * KTOP];

    for (int it = 0; it < KTOP; it++) {
        float m = v[0]; int jm = 0;
        #pragma unroll
        for (int j = 1; j < 16; j++) if (v[j] > m) { m = v[j]; jm = j; }
        float bm = m; int bl = lane;
        #pragma unroll
        for (int off = 16; off; off >>= 1) {
            float om = __shfl_xor_sync(0xffffffffu, bm, off);
            int   ol = __shfl_xor_sync(0xffffffffu, bl, off);
            if (om > bm || (om == bm && ol < bl)) { bm = om; bl = ol; }
        }
        if (bl == lane) {
            ov[it] = m;
            oi[it] = lane * 16 + jm;
            v[jm] = NEG_BIG;
        }
    }
}

// ---------------- sparse 1x1 projection: y[n][o][h][w] = sum_j spv*wp_t[spi][o]
__global__ void k_proj(int layer) {
    int p0 = blockIdx.x * 8;
    __shared__ float sv[8][16];
    __shared__ int   si[8][16];
    int t = threadIdx.x;
    if (t < 128) {
        int pp = t / 16, j = t % 16;
        sv[pp][j] = g_spv[layer][(p0 + pp) * KTOP + j];
        si[pp][j] = g_spi[layer][(p0 + pp) * KTOP + j] * CO;
    }
    __syncthreads();
    const float* wp = g_wp_t[layer];
    float* y = layer ? g_y1 : g_y0;
    int o = t % 128, half = t / 128;
    for (int q = 0; q < 4; q++) {
        int pp = half * 4 + q;
        float acc = 0.f;
        #pragma unroll
        for (int j = 0; j < 16; j++) acc += sv[pp][j] * wp[si[pp][j] + o];
        int p = p0 + pp;
        int n = p / 784, hw = p % 784;
        y[(n * CO + o) * 784 + hw] = acc;
    }
}

// ---------------- shortcut 1x1 stride-2 conv ----------------
__global__ void k_shortcut(const float* __restrict__ x) {
    int pb = blockIdx.x;             // 2 pixels per block
    __shared__ float xsh[2][64];
    int t = threadIdx.x;
    if (t < 128) {
        int pp = t / 64, c = t % 64;
        int p = pb * 2 + pp;
        int n = p / 784, hw = p % 784;
        int h = hw / 28, w = hw % 28;
        xsh[pp][c] = x[((n * C0 + c) * H0 + 2 * h) * H0 + 2 * w];
    }
    __syncthreads();
    int o = t % 128, pp = t / 128;
    float acc = 0.f;
    #pragma unroll
    for (int c = 0; c < 64; c++) acc += xsh[pp][c] * g_wsc_t[c * CO + o];
    int p = pb * 2 + pp;
    int n = p / 784, hw = p % 784;
    g_ysc[(n * CO + o) * 784 + hw] = acc;
}

// ---------------- per-channel batch stats ----------------
__global__ void k_stats(int set) {
    const float* y = (set == 0) ? g_y0 : (set == 1) ? g_y1 : g_ysc;
    int o = blockIdx.x;
    int n0 = blockIdx.y * 8;
    float s = 0.f, s2 = 0.f;
    for (int n = n0; n < n0 + 8; n++) {
        const float* row = y + (size_t)(n * CO + o) * 784;
        for (int i = threadIdx.x; i < 784; i += 256) {
            float v = row[i]; s += v; s2 += v * v;
        }
    }
    __shared__ float sh[16];
    int lane = threadIdx.x & 31, wid = threadIdx.x >> 5;
    #pragma unroll
    for (int off = 16; off; off >>= 1) {
        s  += __shfl_down_sync(0xffffffffu, s, off);
        s2 += __shfl_down_sync(0xffffffffu, s2, off);
    }
    if (lane == 0) { sh[wid] = s; sh[wid + 8] = s2; }
    __syncthreads();
    if (threadIdx.x == 0) {
        float ts = 0.f, ts2 = 0.f;
        for (int w = 0; w < 8; w++) { ts += sh[w]; ts2 += sh[w + 8]; }
        atomicAdd(&g_sum[set][o], (double)ts);
        atomicAdd(&g_sumsq[set][o], (double)ts2);
    }
}

__global__ void k_finalize(int set, const float* __restrict__ g, const float* __restrict__ b) {
    int o = threadIdx.x;
    if (o < CO) {
        double M = (double)PIX;
        double mean = g_sum[set][o] / M;
        double var  = g_sumsq[set][o] / M - mean * mean;
        double sc = (double)g[o] / sqrt(var + 1e-5);
        g_scale[set][o] = (float)sc;
        g_shift[set][o] = (float)((double)b[o] - mean * sc);
    }
}

// ---------------- aux losses (exact conv adjoints, coalesced c-parallel gather)
// aux0: block = 64 threads (one per input channel c), one input pixel per block.
__global__ __launch_bounds__(64) void k_aux0(const float* __restrict__ x) {
    int b  = blockIdx.x;                 // n*56*56 + ih*56 + iw
    int iw = b % 56;
    int ih = (b / 56) % 56;
    int n  = b / (56 * 56);
    int t  = threadIdx.x;                // c

    __shared__ float sv[9][16];
    __shared__ int   si[9][16];

    // cooperative load of sparse codes for valid taps
    for (int idx = t; idx < 144; idx += 64) {
        int kk = idx / 16, j = idx % 16;
        int kh = kk / 3, kw = kk % 3;
        int th = ih + 1 - kh, tw = iw + 1 - kw;
        if (!(th & 1) && !(tw & 1) && th >= 0 && tw >= 0) {
            int oh = th >> 1, ow = tw >> 1;
            if (oh < 28 && ow < 28) {
                int p = (n * 28 + oh) * 28 + ow;
                sv[kk][j] = g_spv[0][p * KTOP + j];
                si[kk][j] = g_spi[0][p * KTOP + j] * (9 * C0);
            }
        }
    }
    __syncthreads();

    float r = 0.f;
    #pragma unroll
    for (int kk = 0; kk < 9; kk++) {
        int kh = kk / 3, kw = kk % 3;
        int th = ih + 1 - kh, tw = iw + 1 - kw;
        if ((th & 1) || (tw & 1) || th < 0 || tw < 0) continue;
        if ((th >> 1) >= 28 || (tw >> 1) >= 28) continue;
        const float* wb = g_wr0 + kk * C0 + t;
        #pragma unroll
        for (int j = 0; j < 16; j++) r += sv[kk][j] * wb[si[kk][j]];
    }
    float df = r - x[((n * C0 + t) * H0 + ih) * H0 + iw];
    float d = df * df;

    // reduce over 64 threads (2 warps)
    #pragma unroll
    for (int off = 16; off; off >>= 1) d += __shfl_down_sync(0xffffffffu, d, off);
    __shared__ float sh[2];
    int lane = t & 31, wid = t >> 5;
    if (lane == 0) sh[wid] = d;
    __syncthreads();
    if (t == 0) atomicAdd(&g_aux_part[0][b & 255], (double)(sh[0] + sh[1]));
}

// aux1: block = 128 threads (one per channel c), one pixel per block.
__global__ __launch_bounds__(128) void k_aux1() {
    int p  = blockIdx.x;                 // 0..PIX-1
    int hw = p % 784;
    int n  = p / 784;
    int ih = hw / 28, iw = hw % 28;
    int t  = threadIdx.x;                // c

    __shared__ float sv[9][16];
    __shared__ int   si[9][16];

    for (int idx = t; idx < 144; idx += 128) {
        int kk = idx / 16, j = idx % 16;
        int kh = kk / 3, kw = kk % 3;
        int oh = ih + 1 - kh, ow = iw + 1 - kw;
        if (oh >= 0 && oh < 28 && ow >= 0 && ow < 28) {
            int pp = (n * 28 + oh) * 28 + ow;
            sv[kk][j] = g_spv[1][pp * KTOP + j];
            si[kk][j] = g_spi[1][pp * KTOP + j] * (9 * CO);
        }
    }
    __syncthreads();

    float r = 0.f;
    #pragma unroll
    for (int kk = 0; kk < 9; kk++) {
        int kh = kk / 3, kw = kk % 3;
        int oh = ih + 1 - kh, ow = iw + 1 - kw;
        if (oh < 0 || oh >= 28 || ow < 0 || ow >= 28) continue;
        const float* wb = g_wr1 + kk * CO + t;
        #pragma unroll
        for (int j = 0; j < 16; j++) r += sv[kk][j] * wb[si[kk][j]];
    }
    float out0 = g_y0[((n * CO + t) * 28 + ih) * 28 + iw] * g_scale[0][t] + g_shift[0][t];
    float df = r - out0;
    float d = df * df;

    #pragma unroll
    for (int off = 16; off; off >>= 1) d += __shfl_down_sync(0xffffffffu, d, off);
    __shared__ float sh[4];
    int lane = t & 31, wid = t >> 5;
    if (lane == 0) sh[wid] = d;
    __syncthreads();
    if (t == 0) atomicAdd(&g_aux_part[1][p & 255], (double)(sh[0] + sh[1] + sh[2] + sh[3]));
}

// ---------------- final fuse: relu(BN1(y1) + BNsc(ysc)) ----------------
__global__ void k_final(float* __restrict__ out) {
    int i = blockIdx.x * 256 + threadIdx.x;   // OUT_ELEMS exactly
    int o = (i / 784) % 128;
    float a = g_y1[i]  * g_scale[1][o] + g_shift[1][o];
    float s = g_ysc[i] * g_scale[2][o] + g_shift[2][o];
    float v = a + s;
    out[i] = v > 0.f ? v : 0.f;
}

__global__ void k_auxwrite(float* __restrict__ out) {
    if (threadIdx.x == 0 && blockIdx.x == 0) {
        double s0 = 0.0, s1 = 0.0;
        for (int i = 0; i < 256; i++) { s0 += g_aux_part[0][i]; s1 += g_aux_part[1][i]; }
        out[OUT_ELEMS]     = (float)(s0 / (double)X_ELEMS);
        out[OUT_ELEMS + 1] = (float)(s1 / (double)OUT_ELEMS);
    }
}

// ---------------- launch ----------------
extern "C" void kernel_launch(void* const* d_in, const int* in_sizes, int n_in,
                              void* d_out, int out_size) {
    const float* x   = (const float*)d_in[0];
    const float* we0 = (const float*)d_in[1];
    const float* wp0 = (const float*)d_in[2];
    const float* g0  = (const float*)d_in[3];
    const float* b0  = (const float*)d_in[4];
    const float* we1 = (const float*)d_in[5];
    const float* wp1 = (const float*)d_in[6];
    const float* g1  = (const float*)d_in[7];
    const float* b1  = (const float*)d_in[8];
    const float* wsc = (const float*)d_in[9];
    const float* gsc = (const float*)d_in[10];
    const float* bsc = (const float*)d_in[11];
    float* out = (float*)d_out;

    (void)in_sizes; (void)n_in; (void)out_size;

    k_zero<<<1, 512>>>();
    k_tr_proj<<<(FS * CO + 255) / 256, 256>>>(wp0, 0);
    k_tr_proj<<<(FS * CO + 255) / 256, 256>>>(wp1, 1);
    k_tr_sc<<<(CO * C0 + 255) / 256, 256>>>(wsc);
    k_tr_enc<<<(FS * C0 * 9 + 255) / 256, 256>>>(we0, 0, C0);
    k_tr_enc<<<(FS * CO * 9 + 255) / 256, 256>>>(we1, 1, CO);

    // layer 0
    k_conv_enc0<<<NB * 14, 512>>>(x);
    k_topk<<<(PIX * 32 + 255) / 256, 256>>>(0);
    k_proj<<<PIX / 8, 256>>>(0);
    {
        dim3 g(CO, 8);
        k_stats<<<g, 256>>>(0);
    }
    k_finalize<<<1, 128>>>(0, g0, b0);

    // layer 1 (reads BN0(y0) on the fly)
    k_conv_enc1<<<NB * 14, 512>>>();
    k_topk<<<(PIX * 32 + 255) / 256, 256>>>(1);
    k_proj<<<PIX / 8, 256>>>(1);
    {
        dim3 g(CO, 8);
        k_stats<<<g, 256>>>(1);
    }
    k_finalize<<<1, 128>>>(1, g1, b1);

    // shortcut
    k_shortcut<<<PIX / 2, 256>>>(x);
    {
        dim3 g(CO, 8);
        k_stats<<<g, 256>>>(2);
    }
    k_finalize<<<1, 128>>>(2, gsc, bsc);

    // aux losses
    k_aux0<<<NB * H0 * H0, 64>>>(x);
    k_aux1<<<PIX, 128>>>();

    // output
    k_final<<<OUT_ELEMS / 256, 256>>>(out);
    k_auxwrite<<<1, 32>>>(out);
}